// round 3
// baseline (speedup 1.0000x reference)
#include <cuda_runtime.h>
#include <cuda_bf16.h>
#include <float.h>

// Problem constants
#define BB 2
#define HH 16
#define SS 2048
#define DD 128
#define BM 64
#define BN 64
#define NTHREADS 256
#define NTILES (SS / BM)

// Shared memory: Qs/Ks/Vs as float4[64][32] (XOR swizzled), Ps as float[64][68]
#define SMEM_BYTES (3 * 64 * 32 * 16 + 64 * 68 * 4)

__global__ __launch_bounds__(NTHREADS, 1)
void attn_flash_fp32_kernel(const float* __restrict__ Q,
                            const float* __restrict__ K,
                            const float* __restrict__ V,
                            const float* __restrict__ AM,   // [B,1,1,S] additive
                            const float* __restrict__ HM,   // [1,H,1,1] multiplicative
                            const float* __restrict__ CTX,  // [B,S]     post-softmax
                            float* __restrict__ out)
{
    extern __shared__ char smem_raw[];
    float4* Qs = reinterpret_cast<float4*>(smem_raw);
    float4* Ks = Qs + 64 * 32;
    float4* Vs = Ks + 64 * 32;
    float*  Ps = reinterpret_cast<float*>(Vs + 64 * 32);

    const int tid = threadIdx.x;
    const int ty  = tid >> 4;   // 0..15 : query-group
    const int tx  = tid & 15;   // 0..15 : key-group / dim-group

    // Reverse so the heaviest CTAs (largest causal extent) launch first.
    const int it = (gridDim.x - 1) - blockIdx.x;
    const int h  = blockIdx.y;
    const int b  = blockIdx.z;
    const int q0 = it * BM;

    const float* Qp = Q + (((size_t)b * HH + h) * SS + q0) * DD;
    const float* Kb = K + (((size_t)b * HH + h) * SS) * DD;
    const float* Vb = V + (((size_t)b * HH + h) * SS) * DD;

    // ---- Load Q tile, swizzled: phys g = g ^ (row & 7) ----
    #pragma unroll
    for (int r = 0; r < 8; ++r) {
        int flat = tid + r * NTHREADS;      // 0..2047
        int row  = flat >> 5;               // 0..63
        int g    = flat & 31;               // 0..31
        Qs[row * 32 + (g ^ (row & 7))] = ((const float4*)Qp)[row * 32 + g];
    }

    // O fragment: 4 query rows x (2 x float4) dims.  dims: [4*tx..4*tx+3] and [64+4*tx..64+4*tx+3]
    float o[4][2][4];
    #pragma unroll
    for (int i = 0; i < 4; ++i)
        #pragma unroll
        for (int e = 0; e < 2; ++e)
            #pragma unroll
            for (int c = 0; c < 4; ++c) o[i][e][c] = 0.f;

    float mrun[4], zrun[4];
    #pragma unroll
    for (int i = 0; i < 4; ++i) { mrun[i] = -FLT_MAX; zrun[i] = 0.f; }

    for (int jt = 0; jt <= it; ++jt) {
        const int kbase = jt * BN;

        __syncthreads();  // protect Ks/Vs/Ps reuse from previous iteration

        // ---- Load K and V tiles (swizzled) ----
        const float4* Kg = (const float4*)(Kb + (size_t)kbase * DD);
        const float4* Vg = (const float4*)(Vb + (size_t)kbase * DD);
        #pragma unroll
        for (int r = 0; r < 8; ++r) {
            int flat = tid + r * NTHREADS;
            int row  = flat >> 5;
            int g    = flat & 31;
            int sidx = row * 32 + (g ^ (row & 7));
            Ks[sidx] = Kg[row * 32 + g];
            Vs[sidx] = Vg[row * 32 + g];
        }

        float amv[4], cxv[4];
        #pragma unroll
        for (int j = 0; j < 4; ++j) {
            int kg = kbase + tx + 16 * j;
            amv[j] = AM[(size_t)b * SS + kg];
            cxv[j] = CTX[(size_t)b * SS + kg];
        }
        __syncthreads();

        // ---- S = Q K^T  (4x4 fragment per thread) ----
        float acc[4][4];
        #pragma unroll
        for (int i = 0; i < 4; ++i)
            #pragma unroll
            for (int j = 0; j < 4; ++j) acc[i][j] = 0.f;

        const int swq = ty & 7;
        const int swk = tx & 7;
        #pragma unroll 8
        for (int g = 0; g < 32; ++g) {
            float4 qf[4], kf[4];
            int gq = g ^ swq;
            int gk = g ^ swk;
            #pragma unroll
            for (int i = 0; i < 4; ++i) qf[i] = Qs[(ty + 16 * i) * 32 + gq];
            #pragma unroll
            for (int j = 0; j < 4; ++j) kf[j] = Ks[(tx + 16 * j) * 32 + gk];
            #pragma unroll
            for (int i = 0; i < 4; ++i)
                #pragma unroll
                for (int j = 0; j < 4; ++j) {
                    acc[i][j] += qf[i].x * kf[j].x;
                    acc[i][j] += qf[i].y * kf[j].y;
                    acc[i][j] += qf[i].z * kf[j].z;
                    acc[i][j] += qf[i].w * kf[j].w;
                }
        }

        // ---- Masks + online softmax ----
        const bool diag = (jt == it);
        #pragma unroll
        for (int i = 0; i < 4; ++i) {
            const int qg = q0 + ty + 16 * i;
            float l[4];
            #pragma unroll
            for (int j = 0; j < 4; ++j) {
                int kg = kbase + tx + 16 * j;
                float v = acc[i][j];
                if (diag && kg > qg) v = -3.402823466e38f;  // finfo(f32).min
                l[j] = v + amv[j];                           // additive mask AFTER causal
            }
            float mt = fmaxf(fmaxf(l[0], l[1]), fmaxf(l[2], l[3]));
            #pragma unroll
            for (int off = 8; off > 0; off >>= 1)
                mt = fmaxf(mt, __shfl_xor_sync(0xffffffffu, mt, off));
            float mnew  = fmaxf(mrun[i], mt);
            float alpha = __expf(mrun[i] - mnew);
            mrun[i] = mnew;

            float zl = 0.f;
            #pragma unroll
            for (int j = 0; j < 4; ++j) {
                float p = __expf(l[j] - mnew);
                zl += p;                                        // Z uses UNSCALED p
                Ps[(ty + 16 * i) * 68 + tx + 16 * j] = p * cxv[j];  // ctx applied post-softmax
            }
            #pragma unroll
            for (int off = 8; off > 0; off >>= 1)
                zl += __shfl_xor_sync(0xffffffffu, zl, off);
            zrun[i] = zrun[i] * alpha + zl;

            #pragma unroll
            for (int e = 0; e < 2; ++e)
                #pragma unroll
                for (int c = 0; c < 4; ++c) o[i][e][c] *= alpha;
        }
        __syncthreads();

        // ---- O += P V  (4 rows x 8 dims per thread) ----
        #pragma unroll 4
        for (int k4 = 0; k4 < 16; ++k4) {
            float4 pf[4];
            #pragma unroll
            for (int i = 0; i < 4; ++i)
                pf[i] = *(const float4*)&Ps[(ty + 16 * i) * 68 + k4 * 4];
            #pragma unroll
            for (int kk = 0; kk < 4; ++kk) {
                int k  = k4 * 4 + kk;
                int sw = k & 7;
                float4 v0 = Vs[k * 32 + (tx ^ sw)];
                float4 v1 = Vs[k * 32 + ((tx + 16) ^ sw)];
                #pragma unroll
                for (int i = 0; i < 4; ++i) {
                    float p = (kk == 0) ? pf[i].x : (kk == 1) ? pf[i].y
                            : (kk == 2) ? pf[i].z : pf[i].w;
                    o[i][0][0] += p * v0.x; o[i][0][1] += p * v0.y;
                    o[i][0][2] += p * v0.z; o[i][0][3] += p * v0.w;
                    o[i][1][0] += p * v1.x; o[i][1][1] += p * v1.y;
                    o[i][1][2] += p * v1.z; o[i][1][3] += p * v1.w;
                }
            }
        }
    }

    // ---- Epilogue: /Z, * head_mask, store ----
    const float hm = HM[h];
    float* Op = out + (((size_t)b * HH + h) * SS + q0) * DD;
    #pragma unroll
    for (int i = 0; i < 4; ++i) {
        float inv = hm / zrun[i];
        int row = ty + 16 * i;
        #pragma unroll
        for (int e = 0; e < 2; ++e) {
            float4 v;
            v.x = o[i][e][0] * inv;
            v.y = o[i][e][1] * inv;
            v.z = o[i][e][2] * inv;
            v.w = o[i][e][3] * inv;
            ((float4*)(Op + (size_t)row * DD))[tx + 16 * e] = v;
        }
    }
}

extern "C" void kernel_launch(void* const* d_in, const int* in_sizes, int n_in,
                              void* d_out, int out_size)
{
    (void)in_sizes; (void)n_in; (void)out_size;
    const float* Q   = (const float*)d_in[0];
    const float* K   = (const float*)d_in[1];
    const float* V   = (const float*)d_in[2];
    const float* AM  = (const float*)d_in[3];
    const float* HM  = (const float*)d_in[4];
    const float* CTX = (const float*)d_in[5];
    float* out = (float*)d_out;

    cudaFuncSetAttribute(attn_flash_fp32_kernel,
                         cudaFuncAttributeMaxDynamicSharedMemorySize, SMEM_BYTES);

    dim3 grid(NTILES, HH, BB);
    attn_flash_fp32_kernel<<<grid, NTHREADS, SMEM_BYTES>>>(Q, K, V, AM, HM, CTX, out);
}